// round 13
// baseline (speedup 1.0000x reference)
#include <cuda_runtime.h>
#include <cstdint>

// GumbelSinkhorn: B=128, N=512 rows, M=512 cols, tau=1, 5 iters.
// Round-10 structure (warp = 1 row x 512 cols, 16-row strips) with
// front-batched unconditional loads (MLP 8) + per-component mask selects.
// ex2 with log2e folded into precomputed reciprocal column scales (g_ics);
// in-kernel colsum inversion via per-batch acq_rel done-counters.

#define BB 128
#define NN 512
#define MM 512
#define LOG2E 1.4426950408889634f

__device__ float    g_E[(size_t)BB * NN * MM];  // exp-domain state
__device__ float    g_acc[5][BB * MM];          // raw colsum accumulators
__device__ float    g_ics[5][BB * MM];          // inverted scales (factor/csum)
__device__ unsigned g_done[5][BB];              // per-batch item counters
__device__ int      g_items[BB * 32];           // 16-row strips: (b<<5)|strip
__device__ int      g_cnt;

__device__ __forceinline__ float ex2f(float x) {
    float y;
    asm("ex2.approx.f32 %0, %1;" : "=f"(y) : "f"(x));
    return y;
}
__device__ __forceinline__ unsigned atom_inc_acqrel(unsigned* p) {
    unsigned old;
    asm volatile("atom.add.acq_rel.gpu.global.u32 %0, [%1], 1;"
                 : "=r"(old) : "l"(p) : "memory");
    return old;
}
__device__ __forceinline__ float ld_cg(const float* p) {
    float v;
    asm volatile("ld.global.cg.f32 %0, [%1];" : "=f"(v) : "l"(p));
    return v;
}
__device__ __forceinline__ float4 ldcs4(const float* p) {
    float4 v;
    asm volatile("ld.global.cs.v4.f32 {%0,%1,%2,%3}, [%4];"
                 : "=f"(v.x), "=f"(v.y), "=f"(v.z), "=f"(v.w) : "l"(p));
    return v;
}
__device__ __forceinline__ void stcs4(float* p, float4 v) {
    asm volatile("st.global.cs.v4.f32 [%0], {%1,%2,%3,%4};"
                 :: "l"(p), "f"(v.x), "f"(v.y), "f"(v.z), "f"(v.w) : "memory");
}
__device__ __forceinline__ float warp_sum(float v) {
    v += __shfl_xor_sync(0xffffffffu, v, 16);
    v += __shfl_xor_sync(0xffffffffu, v, 8);
    v += __shfl_xor_sync(0xffffffffu, v, 4);
    v += __shfl_xor_sync(0xffffffffu, v, 2);
    v += __shfl_xor_sync(0xffffffffu, v, 1);
    return v;
}

// ---------------------------------------------------------------------------
// setup: zero accumulators + done counters; build active-strip list.
__global__ void setup_kernel(const int* __restrict__ fa,
                             const int* __restrict__ ta) {
    float4* p = (float4*)&g_acc[0][0];
    int total4 = 5 * BB * MM / 4;
    int gid = blockIdx.x * blockDim.x + threadIdx.x;
    for (int i = gid; i < total4; i += gridDim.x * blockDim.x)
        p[i] = make_float4(0.f, 0.f, 0.f, 0.f);
    if (gid < 5 * BB) (&g_done[0][0])[gid] = 0u;

    if (blockIdx.x == 0 && threadIdx.x < 32) {
        int lane = threadIdx.x;
        int carry = 0;
        for (int g = 0; g < 4; g++) {
            int b = g * 32 + lane;
            int na = fa[b], nt = ta[b];
            int c = (na > 0 && nt > 0) ? (na + 15) >> 4 : 0;
            int inc = c;
            #pragma unroll
            for (int d = 1; d < 32; d <<= 1) {
                int t = __shfl_up_sync(0xffffffffu, inc, d);
                if (lane >= d) inc += t;
            }
            int off = carry + inc - c;
            for (int s = 0; s < c; s++) g_items[off + s] = (b << 5) | s;
            carry += __shfl_sync(0xffffffffu, inc, 31);
        }
        if (lane == 0) g_cnt = carry;
    }
}

// ---------------------------------------------------------------------------
// Tail: column-partial reduce + atomic accumulate; last finishing CTA of
// batch b inverts the 512 column sums into g_ics[stage].
__device__ __forceinline__ void col_tail(float (*sm)[MM], int stage, float factor,
                                         int b, int na, int nt, int tid) {
    __syncthreads();
    float s = 0.f;
    #pragma unroll
    for (int ww = 0; ww < 16; ww++) s += sm[ww][tid];
    if (tid < nt) atomicAdd(&g_acc[stage][b * MM + tid], s);
    __syncthreads();
    __shared__ bool last;
    if (tid == 0) {
        unsigned items = (unsigned)((na + 15) >> 4);
        last = (atom_inc_acqrel(&g_done[stage][b]) == items - 1u);
    }
    __syncthreads();
    if (last) {
        float ssum = ld_cg(&g_acc[stage][b * MM + tid]);
        g_ics[stage][b * MM + tid] = (ssum > 0.f) ? __fdividef(factor, ssum) : 0.f;
    }
    __syncthreads();
}

// ---------------------------------------------------------------------------
// Shared body. INIT: src=logits (streaming load, scale=LOG2E).
// Pair: src=g_E, per-column ics scales. Loads are unconditional under rowv
// (always in-bounds; masked at compute) so ptxas can front-batch all 8 LDGs.
template<bool INIT>
__device__ __forceinline__ void pair_body(
        const float* __restrict__ src_base, int stage, float factor,
        const float* __restrict__ ics,
        const int* __restrict__ fa, const int* __restrict__ ta,
        float (*sm)[MM]) {
    int cnt = g_cnt;
    int tid = threadIdx.x, w = tid >> 5, lane = tid & 31;
    for (int it = blockIdx.x; it < cnt; it += gridDim.x) {
        int item = g_items[it];
        int b = item >> 5, r0 = (item & 31) << 4;
        int na = fa[b], nt = ta[b];
        const float* CS = ics + b * MM;
        float*       Eb = g_E + (size_t)b * NN * MM;
        int gr = r0 + w;
        bool rowv = (gr < na);
        const float* Sr = src_base + (size_t)b * NN * MM + (size_t)gr * MM;

        // ---- front-batched loads (MLP 8) ----
        float4 eb[4], sb[4];
        if (rowv) {
            #pragma unroll
            for (int k = 0; k < 4; k++) {
                int cb = lane * 4 + k * 128;
                eb[k] = INIT ? ldcs4(Sr + cb) : *(const float4*)(Sr + cb);
                if (!INIT) sb[k] = *(const float4*)(CS + cb);
            }
        }

        // ---- sweep1: v = ex2(scale * e), masked per component ----
        float4 v[4];
        float racc = 0.f;
        #pragma unroll
        for (int k = 0; k < 4; k++) {
            int cb = lane * 4 + k * 128;
            v[k] = make_float4(0.f, 0.f, 0.f, 0.f);
            if (rowv) {
                float sx = INIT ? LOG2E : sb[k].x;
                float sy = INIT ? LOG2E : sb[k].y;
                float sz = INIT ? LOG2E : sb[k].z;
                float sw = INIT ? LOG2E : sb[k].w;
                v[k].x = (cb     < nt) ? ex2f(eb[k].x * sx) : 0.f;
                v[k].y = (cb + 1 < nt) ? ex2f(eb[k].y * sy) : 0.f;
                v[k].z = (cb + 2 < nt) ? ex2f(eb[k].z * sz) : 0.f;
                v[k].w = (cb + 3 < nt) ? ex2f(eb[k].w * sw) : 0.f;
                racc += (v[k].x + v[k].y) + (v[k].z + v[k].w);
            }
        }
        float rinv = __fdividef(LOG2E, warp_sum(racc));

        // ---- sweep2: o = ex2(v * rinv), store E + smem partials ----
        #pragma unroll
        for (int k = 0; k < 4; k++) {
            int cb = lane * 4 + k * 128;
            float4 o = make_float4(0.f, 0.f, 0.f, 0.f);
            if (rowv && cb < nt) {
                o.x = ex2f(v[k].x * rinv);
                o.y = (cb + 1 < nt) ? ex2f(v[k].y * rinv) : 0.f;
                o.z = (cb + 2 < nt) ? ex2f(v[k].z * rinv) : 0.f;
                o.w = (cb + 3 < nt) ? ex2f(v[k].w * rinv) : 0.f;
                *(float4*)(Eb + (size_t)gr * MM + cb) = o;
            }
            *(float4*)(&sm[w][cb]) = o;
        }
        col_tail(sm, stage, factor, b, na, nt, tid);
    }
}

__global__ void __launch_bounds__(512) init_pair_kernel(
        const float* __restrict__ logits,
        const int* __restrict__ fa, const int* __restrict__ ta) {
    __shared__ float sm[16][MM];
    pair_body<true>(logits, 0, LOG2E, &g_ics[0][0], fa, ta, sm);
}

__global__ void __launch_bounds__(512) pair_kernel(
        int p, const int* __restrict__ fa, const int* __restrict__ ta) {
    __shared__ float sm[16][MM];
    float factor = (p == 3) ? 1.0f : LOG2E;
    pair_body<false>(g_E, p + 1, factor, &g_ics[p][0], fa, ta, sm);
}

// ---------------------------------------------------------------------------
// F: out = E9 * ics[4] in mask, 0 outside. Full [N,M], streaming stores.
__global__ void __launch_bounds__(512) final_kernel(
        float* __restrict__ out,
        const int* __restrict__ fa, const int* __restrict__ ta) {
    int b = blockIdx.x >> 5, r0 = (blockIdx.x & 31) << 4;
    int na = fa[b], nt = ta[b];
    int tid = threadIdx.x, w = tid >> 5, lane = tid & 31;
    const float* Eb = g_E + (size_t)b * NN * MM;
    const float* CS = &g_ics[4][0] + b * MM;
    float*       Ob = out + (size_t)b * NN * MM;
    int gr = r0 + w;
    bool rowv = (gr < na);
    #pragma unroll
    for (int k = 0; k < 4; k++) {
        int cb = lane * 4 + k * 128;
        float4 o = make_float4(0.f, 0.f, 0.f, 0.f);
        if (rowv && cb < nt) {
            float4 s4 = *(const float4*)(CS + cb);
            float4 e  = ldcs4(Eb + gr * MM + cb);
            o.x = e.x * s4.x; o.y = e.y * s4.y;
            o.z = e.z * s4.z; o.w = e.w * s4.w;
        }
        stcs4(Ob + gr * MM + cb, o);
    }
}

extern "C" void kernel_launch(void* const* d_in, const int* in_sizes, int n_in,
                              void* d_out, int out_size) {
    const float* logits = (const float*)d_in[0];
    const int*   fa     = (const int*)d_in[1];
    const int*   ta     = (const int*)d_in[2];
    float*       out    = (float*)d_out;

    setup_kernel<<<256, 256>>>(fa, ta);
    init_pair_kernel<<<2048, 512>>>(logits, fa, ta);
    for (int p = 0; p < 4; p++)
        pair_kernel<<<2048, 512>>>(p, fa, ta);
    final_kernel<<<4096, 512>>>(out, fa, ta);
}

// round 14
// speedup vs baseline: 1.2945x; 1.2945x over previous
#include <cuda_runtime.h>
#include <cstdint>

// GumbelSinkhorn: B=128, N=512 rows, M=512 cols, tau=1, 5 iters.
// Round-10 structure (warp = 1 row x 512 cols, 16-row strips, regs ~32) with
// COMPACT E storage: per-batch slab, row stride ntup=ceil128(nt), base from a
// prefix sum over ceil16(na)*16*ntup -> ~44 MB avg, L2-resident across passes.
// ex2 with log2e folded into precomputed reciprocal column scales (g_ics);
// in-kernel colsum inversion via per-batch acq_rel done-counters.

#define BB 128
#define NN 512
#define MM 512
#define LOG2E 1.4426950408889634f

__device__ float    g_E[(size_t)BB * NN * MM];  // compact exp-domain state
__device__ float    g_acc[5][BB * MM];          // raw colsum accumulators
__device__ float    g_ics[5][BB * MM];          // inverted scales (factor/csum)
__device__ unsigned g_done[5][BB];              // per-batch item counters
__device__ int      g_items[BB * 32];           // 16-row strips: (b<<5)|strip
__device__ int      g_ebase[BB];                // compact slab base (elements)
__device__ int      g_cnt;

__device__ __forceinline__ float ex2f(float x) {
    float y;
    asm("ex2.approx.f32 %0, %1;" : "=f"(y) : "f"(x));
    return y;
}
__device__ __forceinline__ unsigned atom_inc_acqrel(unsigned* p) {
    unsigned old;
    asm volatile("atom.add.acq_rel.gpu.global.u32 %0, [%1], 1;"
                 : "=r"(old) : "l"(p) : "memory");
    return old;
}
__device__ __forceinline__ float ld_cg(const float* p) {
    float v;
    asm volatile("ld.global.cg.f32 %0, [%1];" : "=f"(v) : "l"(p));
    return v;
}
__device__ __forceinline__ float4 ldcs4(const float* p) {
    float4 v;
    asm volatile("ld.global.cs.v4.f32 {%0,%1,%2,%3}, [%4];"
                 : "=f"(v.x), "=f"(v.y), "=f"(v.z), "=f"(v.w) : "l"(p));
    return v;
}
__device__ __forceinline__ void stcs4(float* p, float4 v) {
    asm volatile("st.global.cs.v4.f32 [%0], {%1,%2,%3,%4};"
                 :: "l"(p), "f"(v.x), "f"(v.y), "f"(v.z), "f"(v.w) : "memory");
}
__device__ __forceinline__ float warp_sum(float v) {
    v += __shfl_xor_sync(0xffffffffu, v, 16);
    v += __shfl_xor_sync(0xffffffffu, v, 8);
    v += __shfl_xor_sync(0xffffffffu, v, 4);
    v += __shfl_xor_sync(0xffffffffu, v, 2);
    v += __shfl_xor_sync(0xffffffffu, v, 1);
    return v;
}

// ---------------------------------------------------------------------------
// setup: zero accumulators + done counters; build active-strip list AND the
// compact-slab base offsets (prefix over ceil16(na)*16*ntup).
__global__ void setup_kernel(const int* __restrict__ fa,
                             const int* __restrict__ ta) {
    float4* p = (float4*)&g_acc[0][0];
    int total4 = 5 * BB * MM / 4;
    int gid = blockIdx.x * blockDim.x + threadIdx.x;
    for (int i = gid; i < total4; i += gridDim.x * blockDim.x)
        p[i] = make_float4(0.f, 0.f, 0.f, 0.f);
    if (gid < 5 * BB) (&g_done[0][0])[gid] = 0u;

    if (blockIdx.x == 0 && threadIdx.x < 32) {
        int lane = threadIdx.x;
        int carryI = 0, carryE = 0;
        for (int g = 0; g < 4; g++) {
            int b = g * 32 + lane;
            int na = fa[b], nt = ta[b];
            bool act = (na > 0) && (nt > 0);
            int strips = act ? (na + 15) >> 4 : 0;
            int ntup   = act ? ((nt + 127) & ~127) : 0;
            int esz    = strips * 16 * ntup;
            int incI = strips, incE = esz;
            #pragma unroll
            for (int d = 1; d < 32; d <<= 1) {
                int tI = __shfl_up_sync(0xffffffffu, incI, d);
                int tE = __shfl_up_sync(0xffffffffu, incE, d);
                if (lane >= d) { incI += tI; incE += tE; }
            }
            int offI = carryI + incI - strips;
            g_ebase[b] = carryE + incE - esz;
            for (int s = 0; s < strips; s++) g_items[offI + s] = (b << 5) | s;
            carryI += __shfl_sync(0xffffffffu, incI, 31);
            carryE += __shfl_sync(0xffffffffu, incE, 31);
        }
        if (lane == 0) g_cnt = carryI;
    }
}

// ---------------------------------------------------------------------------
// Tail: column-partial reduce (only active columns) + atomic accumulate; the
// last finishing CTA of batch b inverts the 512 colsums into g_ics[stage].
// No trailing barrier: inverting threads never touch sm; racing threads must
// pass the next item's two barriers before `last` can be rewritten.
__device__ __forceinline__ void col_tail(float (*sm)[MM], int stage, float factor,
                                         int b, int na, int nt, int tid) {
    __syncthreads();
    if (tid < nt) {
        float s = 0.f;
        #pragma unroll
        for (int ww = 0; ww < 16; ww++) s += sm[ww][tid];
        atomicAdd(&g_acc[stage][b * MM + tid], s);
    }
    __syncthreads();
    __shared__ bool last;
    if (tid == 0) {
        unsigned items = (unsigned)((na + 15) >> 4);
        last = (atom_inc_acqrel(&g_done[stage][b]) == items - 1u);
    }
    __syncthreads();
    if (last) {
        float ssum = ld_cg(&g_acc[stage][b * MM + tid]);
        g_ics[stage][b * MM + tid] = (ssum > 0.f) ? __fdividef(factor, ssum) : 0.f;
    }
}

// ---------------------------------------------------------------------------
// Shared body. INIT: src = logits (stride MM, streaming); else src = compact E.
// Dest is always the compact E slab.
template<bool INIT>
__device__ __forceinline__ void pair_body(
        const float* __restrict__ logits, int stage, float factor,
        const float* __restrict__ ics,
        const int* __restrict__ fa, const int* __restrict__ ta,
        float (*sm)[MM]) {
    int cnt = g_cnt;
    int tid = threadIdx.x, w = tid >> 5, lane = tid & 31;
    for (int it = blockIdx.x; it < cnt; it += gridDim.x) {
        int item = g_items[it];
        int b = item >> 5, r0 = (item & 31) << 4;
        int na = fa[b], nt = ta[b];
        int ntup = (nt + 127) & ~127;
        const float* CS = ics + b * MM;
        int gr = r0 + w;
        bool rowv = (gr < na);
        float* Ew = g_E + g_ebase[b] + gr * ntup;          // compact row
        const float* Sr = INIT
            ? (logits + (size_t)b * NN * MM + (size_t)gr * MM)
            : Ew;

        // ---- sweep1: v = ex2(scale * e) ----
        float4 v[4];
        float racc = 0.f;
        #pragma unroll
        for (int k = 0; k < 4; k++) {
            int cb = lane * 4 + k * 128;
            v[k] = make_float4(0.f, 0.f, 0.f, 0.f);
            if (rowv && cb < nt) {
                float4 e = INIT ? ldcs4(Sr + cb) : *(const float4*)(Sr + cb);
                if (INIT) {
                    v[k].x = ex2f(e.x * LOG2E);
                    v[k].y = (cb + 1 < nt) ? ex2f(e.y * LOG2E) : 0.f;
                    v[k].z = (cb + 2 < nt) ? ex2f(e.z * LOG2E) : 0.f;
                    v[k].w = (cb + 3 < nt) ? ex2f(e.w * LOG2E) : 0.f;
                } else {
                    float4 s4 = *(const float4*)(CS + cb);
                    v[k].x = ex2f(e.x * s4.x);
                    v[k].y = (cb + 1 < nt) ? ex2f(e.y * s4.y) : 0.f;
                    v[k].z = (cb + 2 < nt) ? ex2f(e.z * s4.z) : 0.f;
                    v[k].w = (cb + 3 < nt) ? ex2f(e.w * s4.w) : 0.f;
                }
                racc += (v[k].x + v[k].y) + (v[k].z + v[k].w);
            }
        }
        float rinv = __fdividef(LOG2E, warp_sum(racc));

        // ---- sweep2: o = ex2(v * rinv), store compact E + smem partials ----
        #pragma unroll
        for (int k = 0; k < 4; k++) {
            int cb = lane * 4 + k * 128;
            float4 o = make_float4(0.f, 0.f, 0.f, 0.f);
            if (rowv && cb < nt) {
                o.x = ex2f(v[k].x * rinv);
                o.y = (cb + 1 < nt) ? ex2f(v[k].y * rinv) : 0.f;
                o.z = (cb + 2 < nt) ? ex2f(v[k].z * rinv) : 0.f;
                o.w = (cb + 3 < nt) ? ex2f(v[k].w * rinv) : 0.f;
                *(float4*)(Ew + cb) = o;
            }
            if (k * 128 < nt)                 // skip fully-inactive blocks
                *(float4*)(&sm[w][cb]) = o;   // zeros where inactive/invalid
        }
        col_tail(sm, stage, factor, b, na, nt, tid);
    }
}

__global__ void __launch_bounds__(512) init_pair_kernel(
        const float* __restrict__ logits,
        const int* __restrict__ fa, const int* __restrict__ ta) {
    __shared__ float sm[16][MM];
    pair_body<true>(logits, 0, LOG2E, &g_ics[0][0], fa, ta, sm);
}

__global__ void __launch_bounds__(512) pair_kernel(
        int p, const int* __restrict__ fa, const int* __restrict__ ta) {
    __shared__ float sm[16][MM];
    float factor = (p == 3) ? 1.0f : LOG2E;
    pair_body<false>(nullptr, p + 1, factor, &g_ics[p][0], fa, ta, sm);
}

// ---------------------------------------------------------------------------
// F: out = E9 * ics[4] in mask, 0 outside. Full [N,M]; compact E read (ldcs),
// streaming out stores (stcs). grid 4096 (b<<5|strip16), warp per row.
__global__ void __launch_bounds__(512) final_kernel(
        float* __restrict__ out,
        const int* __restrict__ fa, const int* __restrict__ ta) {
    int b = blockIdx.x >> 5, r0 = (blockIdx.x & 31) << 4;
    int na = fa[b], nt = ta[b];
    int ntup = (nt + 127) & ~127;
    int tid = threadIdx.x, w = tid >> 5, lane = tid & 31;
    const float* CS = &g_ics[4][0] + b * MM;
    float*       Ob = out + (size_t)b * NN * MM;
    int gr = r0 + w;
    bool rowv = (gr < na);
    const float* Er = g_E + g_ebase[b] + gr * ntup;
    #pragma unroll
    for (int k = 0; k < 4; k++) {
        int cb = lane * 4 + k * 128;
        float4 o = make_float4(0.f, 0.f, 0.f, 0.f);
        if (rowv && cb < nt) {
            float4 s4 = *(const float4*)(CS + cb);
            float4 e  = ldcs4(Er + cb);
            o.x = e.x * s4.x; o.y = e.y * s4.y;
            o.z = e.z * s4.z; o.w = e.w * s4.w;
        }
        stcs4(Ob + gr * MM + cb, o);
    }
}

extern "C" void kernel_launch(void* const* d_in, const int* in_sizes, int n_in,
                              void* d_out, int out_size) {
    const float* logits = (const float*)d_in[0];
    const int*   fa     = (const int*)d_in[1];
    const int*   ta     = (const int*)d_in[2];
    float*       out    = (float*)d_out;

    setup_kernel<<<256, 256>>>(fa, ta);
    init_pair_kernel<<<2048, 512>>>(logits, fa, ta);
    for (int p = 0; p < 4; p++)
        pair_kernel<<<2048, 512>>>(p, fa, ta);
    final_kernel<<<4096, 512>>>(out, fa, ta);
}